// round 4
// baseline (speedup 1.0000x reference)
#include <cuda_runtime.h>
#include <cuda_bf16.h>
#include <math.h>

// Problem constants (fixed by setup_inputs)
#define B_   8
#define LK_  4
#define D_   64
#define L_   4096
#define DEPTH_ 12
#define NQ_  (B_ * LK_)   // 32

// Scratch (static device globals — no runtime allocation)
__device__ float g_s[NQ_ * L_];        // s[b*4+k][leaf]  (512 KB)
__device__ float g_nll[DEPTH_ * NQ_];  // nll[level][bk]
__device__ int   g_labels[NQ_];

// ---------------------------------------------------------------------------
// Kernel 0: decode expected labels (robust to int32 vs int64 storage)
// ---------------------------------------------------------------------------
__global__ void k_decode(const int* __restrict__ e32) {
    __shared__ int oddor;
    if (threadIdx.x == 0) {
        int o = 0;
        #pragma unroll
        for (int t = 1; t < 32; t += 2) o |= e32[t];
        oddor = o;
    }
    __syncthreads();
    int j = threadIdx.x;  // 0..31
    // If stored as little-endian int64, all odd 32-bit words are 0 (labels < 4096).
    g_labels[j] = (oddor == 0) ? e32[2 * j] : e32[j];
}

// ---------------------------------------------------------------------------
// Kernel 1: s[b,k,i] = (q[b,k] . leafs[b,i] . v[b,k]) / 64  for all leaves.
// One warp per leaf. 8 warps / block. Fully coalesced LDG.128 over leafs.
// Per-lane invariant: e0 = 4*(lane&15) is constant -> v in registers.
// q (pre-scaled by 1/64) transposed in shared: qt[d][k], one LDS.128 per chunk.
// ---------------------------------------------------------------------------
__global__ __launch_bounds__(256) void k_leaf_dots(
    const float* __restrict__ q,
    const float* __restrict__ v,
    const float* __restrict__ leafs)
{
    __shared__ float qt[D_ * LK_];  // [d][k], 1 KB

    const int b   = blockIdx.x >> 9;          // 512 blocks per batch
    const int tid = threadIdx.x;

    // Load transposed, pre-scaled q into shared: qt[d*4+k] = q[b,k,d] / 64
    {
        int d = tid >> 2, k = tid & 3;
        qt[tid] = q[((b << 2) + k) * D_ + d] * (1.0f / 64.0f);
    }

    const int lane = tid & 31;
    const int wid  = tid >> 5;
    const int e0   = (lane & 15) << 2;   // column base: constant per lane
    const int hi   = lane >> 4;          // row parity offset

    // v values for this lane's 4 columns, all 4 queries (16 registers)
    const float4 v0 = *(const float4*)&v[((b << 2) + 0) * D_ + e0];
    const float4 v1 = *(const float4*)&v[((b << 2) + 1) * D_ + e0];
    const float4 v2 = *(const float4*)&v[((b << 2) + 2) * D_ + e0];
    const float4 v3 = *(const float4*)&v[((b << 2) + 3) * D_ + e0];

    __syncthreads();

    const int leaf = ((blockIdx.x & 511) << 3) + wid;   // 0..4095 within batch
    const float4* mp =
        (const float4*)(leafs + (((size_t)b << 12) + (size_t)leaf) * (D_ * D_)) + lane;

    float a0 = 0.f, a1 = 0.f, a2 = 0.f, a3 = 0.f;

    #pragma unroll 8
    for (int c = 0; c < 32; ++c) {
        const float4 m  = __ldcs(mp + c * 32);                 // streaming: zero reuse
        const float4 qv = *(const float4*)&qt[(((c << 1) + hi) << 2)]; // q[d][0..3]

        float d0 = m.x * v0.x; d0 = fmaf(m.y, v0.y, d0); d0 = fmaf(m.z, v0.z, d0); d0 = fmaf(m.w, v0.w, d0);
        float d1 = m.x * v1.x; d1 = fmaf(m.y, v1.y, d1); d1 = fmaf(m.z, v1.z, d1); d1 = fmaf(m.w, v1.w, d1);
        float d2 = m.x * v2.x; d2 = fmaf(m.y, v2.y, d2); d2 = fmaf(m.z, v2.z, d2); d2 = fmaf(m.w, v2.w, d2);
        float d3 = m.x * v3.x; d3 = fmaf(m.y, v3.y, d3); d3 = fmaf(m.z, v3.z, d3); d3 = fmaf(m.w, v3.w, d3);

        a0 = fmaf(qv.x, d0, a0);
        a1 = fmaf(qv.y, d1, a1);
        a2 = fmaf(qv.z, d2, a2);
        a3 = fmaf(qv.w, d3, a3);
    }

    // Warp reduction (4 independent chains)
    #pragma unroll
    for (int o = 16; o; o >>= 1) {
        a0 += __shfl_xor_sync(0xffffffffu, a0, o);
        a1 += __shfl_xor_sync(0xffffffffu, a1, o);
        a2 += __shfl_xor_sync(0xffffffffu, a2, o);
        a3 += __shfl_xor_sync(0xffffffffu, a3, o);
    }

    if (lane == 0) {
        const int base = (b << 2);
        g_s[((size_t)(base + 0) << 12) + leaf] = a0;
        g_s[((size_t)(base + 1) << 12) + leaf] = a1;
        g_s[((size_t)(base + 2) << 12) + leaf] = a2;
        g_s[((size_t)(base + 3) << 12) + leaf] = a3;
    }
}

// ---------------------------------------------------------------------------
// Kernel 2: per (b,k), build level logits by pairwise averaging and compute
// nll[level] = logsumexp(logits) - logits[label >> level].
// ---------------------------------------------------------------------------
__global__ __launch_bounds__(256) void k_levels() {
    __shared__ float bufA[L_];       // 16 KB
    __shared__ float bufB[L_ / 2];   //  8 KB
    __shared__ float red[8];
    __shared__ float bc;

    const int bk  = blockIdx.x;      // b*4+k
    const int tid = threadIdx.x;

    const float* srow = g_s + ((size_t)bk << 12);
    for (int i = tid; i < L_; i += 256) bufA[i] = srow[i];
    __syncthreads();

    const int lab = g_labels[bk];

    float* cur = bufA;
    float* nxt = bufB;
    int N = L_;

    for (int level = 0; level < DEPTH_; ++level) {
        // --- block max ---
        float mx = -3.4e38f;
        for (int i = tid; i < N; i += 256) mx = fmaxf(mx, cur[i]);
        #pragma unroll
        for (int o = 16; o; o >>= 1) mx = fmaxf(mx, __shfl_xor_sync(0xffffffffu, mx, o));
        if ((tid & 31) == 0) red[tid >> 5] = mx;
        __syncthreads();
        if (tid == 0) {
            float m = red[0];
            #pragma unroll
            for (int w = 1; w < 8; ++w) m = fmaxf(m, red[w]);
            bc = m;
        }
        __syncthreads();
        mx = bc;

        // --- block sum of exp ---
        float sum = 0.f;
        for (int i = tid; i < N; i += 256) sum += __expf(cur[i] - mx);
        #pragma unroll
        for (int o = 16; o; o >>= 1) sum += __shfl_xor_sync(0xffffffffu, sum, o);
        __syncthreads();                       // red reuse barrier
        if ((tid & 31) == 0) red[tid >> 5] = sum;
        __syncthreads();
        if (tid == 0) {
            float s = 0.f;
            #pragma unroll
            for (int w = 0; w < 8; ++w) s += red[w];
            g_nll[level * NQ_ + bk] = mx + __logf(s) - cur[lab >> level];
        }

        // --- halve (parent = mean of children) ---
        if (level < DEPTH_ - 1) {
            const int half = N >> 1;
            for (int i = tid; i < half; i += 256)
                nxt[i] = 0.5f * (cur[2 * i] + cur[2 * i + 1]);
            __syncthreads();
            float* t = cur; cur = nxt; nxt = t;
            N = half;
        }
    }
}

// ---------------------------------------------------------------------------
// Kernel 3: weighted cross-entropy reduction. The w /= w.sum() normalization
// cancels in per_q = sum_b(wy*nll)/sum_b(wy), so only counts at the 32 label
// positions are needed: w_raw = 32 / (count + 1e-8).
// ---------------------------------------------------------------------------
__global__ void k_final(float* __restrict__ out) {
    const int j = threadIdx.x;  // 0..31 == b*4+k
    __shared__ float wr[NQ_], wn[NQ_];

    const int lab = g_labels[j];
    float total = 0.f;

    for (int level = 0; level < DEPTH_; ++level) {
        const int my = lab >> level;
        int cnt = 0;
        #pragma unroll
        for (int t = 0; t < NQ_; ++t) cnt += ((g_labels[t] >> level) == my);
        const float w = 32.0f / ((float)cnt + 1e-8f);
        wr[j] = w;
        wn[j] = w * g_nll[level * NQ_ + j];
        __syncwarp();
        if (j < 4) {  // j == k
            float num = 0.f, den = 0.f;
            #pragma unroll
            for (int b = 0; b < B_; ++b) {
                num += wn[(b << 2) + j];
                den += wr[(b << 2) + j];
            }
            total += num / den;
        }
        __syncwarp();
    }

    // reduce lanes 0..3
    total += __shfl_xor_sync(0xffffffffu, total, 1);
    total += __shfl_xor_sync(0xffffffffu, total, 2);
    if (j == 0) out[0] = total;
}

// ---------------------------------------------------------------------------
extern "C" void kernel_launch(void* const* d_in, const int* in_sizes, int n_in,
                              void* d_out, int out_size) {
    const float* q        = (const float*)d_in[0];
    const float* v        = (const float*)d_in[1];
    const int*   expected = (const int*)d_in[2];
    const float* leafs    = (const float*)d_in[3];
    float*       out      = (float*)d_out;

    k_decode<<<1, 32>>>(expected);
    k_leaf_dots<<<(B_ * L_) / 8, 256>>>(q, v, leafs);
    k_levels<<<NQ_, 256>>>();
    k_final<<<1, 32>>>(out);
}

// round 5
// speedup vs baseline: 1.0799x; 1.0799x over previous
#include <cuda_runtime.h>
#include <cuda_bf16.h>
#include <math.h>

// Problem constants (fixed by setup_inputs)
#define B_   8
#define LK_  4
#define D_   64
#define L_   4096
#define DEPTH_ 12
#define NQ_  (B_ * LK_)   // 32

// Scratch (static device globals — no runtime allocation)
__device__ float g_s[NQ_ * L_];        // s[b*4+k][leaf]  (512 KB)
__device__ float g_nll[DEPTH_ * NQ_];  // nll[level][bk]

// ---------------------------------------------------------------------------
// Label decode helper: `expected` is logically int64 but may be stored as
// int32. If int64 (little-endian), all odd 32-bit words are 0 (labels<4096).
// ---------------------------------------------------------------------------
__device__ __forceinline__ int decode_label(const int* __restrict__ e32,
                                            int j, bool is64) {
    return is64 ? e32[2 * j] : e32[j];
}

// ---------------------------------------------------------------------------
// Kernel 1: s[b,k,i] = (q[b,k] . leafs[b,i] . v[b,k]) / 64  for all leaves.
// One warp per leaf, 8 warps/block, fully coalesced streaming LDG.128.
// Per-lane column base e0 = 4*(lane&15) is constant -> v in 16 registers.
// q (pre-scaled by 1/64) transposed in shared: one LDS.128 per chunk.
// ---------------------------------------------------------------------------
__global__ __launch_bounds__(256) void k_leaf_dots(
    const float* __restrict__ q,
    const float* __restrict__ v,
    const float* __restrict__ leafs)
{
    __shared__ float qt[D_ * LK_];  // [d][k], 1 KB

    const int b   = blockIdx.x >> 9;          // 512 blocks per batch
    const int tid = threadIdx.x;

    {
        int d = tid >> 2, k = tid & 3;
        qt[tid] = q[((b << 2) + k) * D_ + d] * (1.0f / 64.0f);
    }

    const int lane = tid & 31;
    const int wid  = tid >> 5;
    const int e0   = (lane & 15) << 2;   // column base: constant per lane
    const int hi   = lane >> 4;          // row parity offset

    const float4 v0 = *(const float4*)&v[((b << 2) + 0) * D_ + e0];
    const float4 v1 = *(const float4*)&v[((b << 2) + 1) * D_ + e0];
    const float4 v2 = *(const float4*)&v[((b << 2) + 2) * D_ + e0];
    const float4 v3 = *(const float4*)&v[((b << 2) + 3) * D_ + e0];

    __syncthreads();

    const int leaf = ((blockIdx.x & 511) << 3) + wid;   // 0..4095 within batch
    const float4* mp =
        (const float4*)(leafs + (((size_t)b << 12) + (size_t)leaf) * (D_ * D_)) + lane;

    float a0 = 0.f, a1 = 0.f, a2 = 0.f, a3 = 0.f;

    #pragma unroll 8
    for (int c = 0; c < 32; ++c) {
        const float4 m  = __ldcs(mp + c * 32);                 // streaming: zero reuse
        const float4 qv = *(const float4*)&qt[(((c << 1) + hi) << 2)];

        float d0 = m.x * v0.x; d0 = fmaf(m.y, v0.y, d0); d0 = fmaf(m.z, v0.z, d0); d0 = fmaf(m.w, v0.w, d0);
        float d1 = m.x * v1.x; d1 = fmaf(m.y, v1.y, d1); d1 = fmaf(m.z, v1.z, d1); d1 = fmaf(m.w, v1.w, d1);
        float d2 = m.x * v2.x; d2 = fmaf(m.y, v2.y, d2); d2 = fmaf(m.z, v2.z, d2); d2 = fmaf(m.w, v2.w, d2);
        float d3 = m.x * v3.x; d3 = fmaf(m.y, v3.y, d3); d3 = fmaf(m.z, v3.z, d3); d3 = fmaf(m.w, v3.w, d3);

        a0 = fmaf(qv.x, d0, a0);
        a1 = fmaf(qv.y, d1, a1);
        a2 = fmaf(qv.z, d2, a2);
        a3 = fmaf(qv.w, d3, a3);
    }

    #pragma unroll
    for (int o = 16; o; o >>= 1) {
        a0 += __shfl_xor_sync(0xffffffffu, a0, o);
        a1 += __shfl_xor_sync(0xffffffffu, a1, o);
        a2 += __shfl_xor_sync(0xffffffffu, a2, o);
        a3 += __shfl_xor_sync(0xffffffffu, a3, o);
    }

    if (lane == 0) {
        const int base = (b << 2);
        g_s[((size_t)(base + 0) << 12) + leaf] = a0;
        g_s[((size_t)(base + 1) << 12) + leaf] = a1;
        g_s[((size_t)(base + 2) << 12) + leaf] = a2;
        g_s[((size_t)(base + 3) << 12) + leaf] = a3;
    }
}

// ---------------------------------------------------------------------------
// Kernel 2: per (b,k), build level logits by pairwise averaging and compute
// nll[level] = logsumexp(logits) - logits[label >> level].
// Decodes its own label inline (no separate decode kernel).
// ---------------------------------------------------------------------------
__global__ __launch_bounds__(256) void k_levels(const int* __restrict__ e32) {
    __shared__ float bufA[L_];       // 16 KB
    __shared__ float bufB[L_ / 2];   //  8 KB
    __shared__ float red[8];
    __shared__ float bc;
    __shared__ int   s_lab;

    const int bk  = blockIdx.x;      // b*4+k
    const int tid = threadIdx.x;

    // Warp 0: decode this block's label (parallel int64/int32 detection)
    if (tid < 32) {
        unsigned nz = __ballot_sync(0xffffffffu, e32[2 * tid + 1] != 0);
        if (tid == 0) s_lab = (nz == 0) ? e32[2 * bk] : e32[bk];
    }

    const float* srow = g_s + ((size_t)bk << 12);
    for (int i = tid; i < L_; i += 256) bufA[i] = srow[i];
    __syncthreads();

    const int lab = s_lab;

    float* cur = bufA;
    float* nxt = bufB;
    int N = L_;

    for (int level = 0; level < DEPTH_; ++level) {
        // --- block max ---
        float mx = -3.4e38f;
        for (int i = tid; i < N; i += 256) mx = fmaxf(mx, cur[i]);
        #pragma unroll
        for (int o = 16; o; o >>= 1) mx = fmaxf(mx, __shfl_xor_sync(0xffffffffu, mx, o));
        if ((tid & 31) == 0) red[tid >> 5] = mx;
        __syncthreads();
        if (tid == 0) {
            float m = red[0];
            #pragma unroll
            for (int w = 1; w < 8; ++w) m = fmaxf(m, red[w]);
            bc = m;
        }
        __syncthreads();
        mx = bc;

        // --- block sum of exp ---
        float sum = 0.f;
        for (int i = tid; i < N; i += 256) sum += __expf(cur[i] - mx);
        #pragma unroll
        for (int o = 16; o; o >>= 1) sum += __shfl_xor_sync(0xffffffffu, sum, o);
        __syncthreads();                       // red reuse barrier
        if ((tid & 31) == 0) red[tid >> 5] = sum;
        __syncthreads();
        if (tid == 0) {
            float s = 0.f;
            #pragma unroll
            for (int w = 0; w < 8; ++w) s += red[w];
            g_nll[level * NQ_ + bk] = mx + __logf(s) - cur[lab >> level];
        }

        // --- halve (parent = mean of children) ---
        if (level < DEPTH_ - 1) {
            const int half = N >> 1;
            for (int i = tid; i < half; i += 256)
                nxt[i] = 0.5f * (cur[2 * i] + cur[2 * i + 1]);
            __syncthreads();
            float* t = cur; cur = nxt; nxt = t;
            N = half;
        }
    }
}

// ---------------------------------------------------------------------------
// Kernel 3: weighted cross-entropy reduction, latency-optimized.
// The w /= w.sum() normalization cancels in per_q = Σ_b(wy·nll)/Σ_b(wy), so
// only counts at the 32 label positions are needed: w_raw = 32/(count+1e-8).
// 384 threads: one coalesced LDG each for nll (MLP=384), labels decoded in
// parallel, then 48 threads each own one (level,k) ratio from shared.
// ---------------------------------------------------------------------------
__global__ __launch_bounds__(384) void k_final(const int* __restrict__ e32,
                                               float* __restrict__ out) {
    __shared__ float s_nll[DEPTH_ * NQ_];  // 384 floats
    __shared__ int   s_lab[NQ_];
    __shared__ float s_part[48];

    const int tid = threadIdx.x;

    // Coalesced preload of all nll values (one LDG per thread, full MLP)
    s_nll[tid] = g_nll[tid];

    // Parallel label decode (warp 0)
    if (tid < 32) {
        unsigned nz = __ballot_sync(0xffffffffu, e32[2 * tid + 1] != 0);
        s_lab[tid] = (nz == 0) ? e32[2 * tid] : e32[tid];
    }
    __syncthreads();

    // 48 threads: one (level, k) pair each
    if (tid < 48) {
        const int level = tid >> 2;
        const int k     = tid & 3;
        float num = 0.f, den = 0.f;
        #pragma unroll
        for (int b = 0; b < B_; ++b) {
            const int my = s_lab[(b << 2) + k] >> level;
            int cnt = 0;
            #pragma unroll
            for (int t = 0; t < NQ_; ++t) cnt += ((s_lab[t] >> level) == my);
            const float w = 32.0f / ((float)cnt + 1e-8f);
            num = fmaf(w, s_nll[level * NQ_ + (b << 2) + k], num);
            den += w;
        }
        s_part[tid] = num / den;
    }
    __syncthreads();

    if (tid == 0) {
        float total = 0.f;
        #pragma unroll
        for (int i = 0; i < 48; ++i) total += s_part[i];
        out[0] = total;
    }
}

// ---------------------------------------------------------------------------
extern "C" void kernel_launch(void* const* d_in, const int* in_sizes, int n_in,
                              void* d_out, int out_size) {
    const float* q        = (const float*)d_in[0];
    const float* v        = (const float*)d_in[1];
    const int*   expected = (const int*)d_in[2];
    const float* leafs    = (const float*)d_in[3];
    float*       out      = (float*)d_out;

    k_leaf_dots<<<(B_ * L_) / 8, 256>>>(q, v, leafs);
    k_levels<<<NQ_, 256>>>(expected);
    k_final<<<1, 384>>>(expected, out);
}